// round 17
// baseline (speedup 1.0000x reference)
#include <cuda_runtime.h>
#include <cuda_bf16.h>

#define PADW 68

typedef unsigned long long u64;

// ---- packed f32x2 helpers ----
__device__ __forceinline__ u64 ffma2(u64 a, u64 b, u64 c){
    u64 d; asm("fma.rn.f32x2 %0, %1, %2, %3;" : "=l"(d) : "l"(a), "l"(b), "l"(c)); return d;
}
__device__ __forceinline__ u64 fmul2(u64 a, u64 b){
    u64 d; asm("mul.rn.f32x2 %0, %1, %2;" : "=l"(d) : "l"(a), "l"(b)); return d;
}
__device__ __forceinline__ u64 dup2(float x){
    u64 d; asm("mov.b64 %0, {%1, %1};" : "=l"(d) : "f"(x)); return d;
}
__device__ __forceinline__ float hadd2(u64 a){
    float lo, hi; asm("mov.b64 {%0, %1}, %2;" : "=f"(lo), "=f"(hi) : "l"(a)); return lo + hi;
}
__device__ __forceinline__ int ld_acq(const int* p){
    int v; asm volatile("ld.acquire.gpu.b32 %0, [%1];" : "=r"(v) : "l"(p) : "memory"); return v;
}

// triangular T3 base offsets: base(t) = sum_{t'<t} t'*(8-t')
__device__ __forceinline__ constexpr int B84(int t){
    return (t<=1)?0 : (t==2)?7 : (t==3)?19 : (t==4)?34 : (t==5)?50 : (t==6)?65 : 77;
}

// ---- global scratch ----
__device__ float g_states[2*16*32*64*64];
__device__ float g_y[2*2048*16*64];
// per-task precompute record (stride 2048 floats):
//  [gh 0..511 | Wx 512..1023 | RW 1024..1535 | W8 1536..1599 | P1 1600..1663 | T3 1664..1747 | pad]
#define PRE_STRIDE 2048
#define OG   0
#define OWX  512
#define ORW  1024
#define OW8  1536
#define OP1  1600
#define OT3  1664
__device__ float g_pre[32*256*PRE_STRIDE];
__device__ int   g_ptask[32*256];
__device__ int   g_c1 = 0;
__device__ int   g_c2 = 0;
__device__ int   g_prog[32] = {};

// ---------------------------------------------------------------------------
// SSD chunk body (unchanged, passing since R1).
// ---------------------------------------------------------------------------
__device__ void ssd_chunk_body(int blk, float* sm,
    const float* __restrict__ Xg, const float* __restrict__ Ag,
    const float* __restrict__ Bg, const float* __restrict__ Cg,
    float* __restrict__ out)
{
    float* sC   = sm;
    float* sB   = sC + 64*PADW;
    float* sX   = sB + 64*PADW;
    float* sG   = sX + 64*PADW;
    float* sCum = sG + 64*PADW;
    float* sDec = sCum + 64;

    int c  = blk & 31;
    int bh = blk >> 5;
    int b  = bh >> 4, h = bh & 15;
    int tid = threadIdx.x;

    long long gbase = ((long long)b*2048 + c*64)*1024 + h*64;

    for (int e = tid; e < 4096; e += 256){
        int l = e >> 6, p = e & 63;
        long long gi = gbase + (long long)l*1024 + p;
        int si = l*PADW + p;
        sC[si] = Cg[gi];
        sB[si] = Bg[gi];
        sX[si] = Xg[gi];
    }
    if (tid < 64) sCum[tid] = Ag[((long long)b*2048 + c*64 + tid)*16 + h];
    __syncthreads();
    if (tid == 0){
        float run = 0.f;
        for (int l = 0; l < 64; l++){ run += sCum[l]; sCum[l] = run; }
    }
    __syncthreads();
    if (tid < 64) sDec[tid] = expf(sCum[63] - sCum[tid]);

    int l  = tid >> 2;
    int pg = tid & 3;

    float g[16];
#pragma unroll
    for (int i = 0; i < 16; i++) g[i] = 0.f;
    {
        const float4* c4 = (const float4*)(sC + l*PADW);
#pragma unroll 4
        for (int n4 = 0; n4 < 16; n4++){
            float4 cv = c4[n4];
#pragma unroll
            for (int si = 0; si < 16; si++){
                int s = 4*si + pg;
                float4 bv = ((const float4*)(sB + s*PADW))[n4];
                g[si] += cv.x*bv.x + cv.y*bv.y + cv.z*bv.z + cv.w*bv.w;
            }
        }
    }
    float cuml = sCum[l];
#pragma unroll
    for (int si = 0; si < 16; si++){
        int s = 4*si + pg;
        sG[l*PADW + s] = (s <= l) ? g[si]*expf(cuml - sCum[s]) : 0.f;
    }
    __syncthreads();

    float acc[16];
#pragma unroll
    for (int i = 0; i < 16; i++) acc[i] = 0.f;
    for (int s = 0; s < 64; s++){
        float gv = sG[l*PADW + s];
        const float4* x4 = (const float4*)(sX + s*PADW) + pg*4;
#pragma unroll
        for (int q4 = 0; q4 < 4; q4++){
            float4 xv = x4[q4];
            acc[q4*4+0] += gv*xv.x;
            acc[q4*4+1] += gv*xv.y;
            acc[q4*4+2] += gv*xv.z;
            acc[q4*4+3] += gv*xv.w;
        }
    }
    {
        float4* op = (float4*)(out + gbase + (long long)l*1024 + pg*16);
#pragma unroll
        for (int q4 = 0; q4 < 4; q4++){
            float4 ov;
            ov.x = acc[q4*4+0]; ov.y = acc[q4*4+1];
            ov.z = acc[q4*4+2]; ov.w = acc[q4*4+3];
            op[q4] = ov;
        }
    }

    int pp = tid >> 2, ng = tid & 3;
#pragma unroll
    for (int i = 0; i < 16; i++) acc[i] = 0.f;
    for (int l2 = 0; l2 < 64; l2++){
        float t = sDec[l2] * sX[l2*PADW + pp];
        const float4* b4 = (const float4*)(sB + l2*PADW) + ng*4;
#pragma unroll
        for (int q4 = 0; q4 < 4; q4++){
            float4 bv = b4[q4];
            acc[q4*4+0] += t*bv.x;
            acc[q4*4+1] += t*bv.y;
            acc[q4*4+2] += t*bv.z;
            acc[q4*4+3] += t*bv.w;
        }
    }
    {
        float4* sp = (float4*)(g_states + ((long long)bh*32 + c)*4096 + pp*64 + ng*16);
#pragma unroll
        for (int q4 = 0; q4 < 4; q4++){
            float4 sv;
            sv.x = acc[q4*4+0]; sv.y = acc[q4*4+1];
            sv.z = acc[q4*4+2]; sv.w = acc[q4*4+3];
            sp[q4] = sv;
        }
    }
}

// ---------------------------------------------------------------------------
// Precompute body: state-independent WY quantities per 8-step task.
// 96 blocks: pb in 0..95 -> bw = pb&31, part = pb>>5; tasks blk8 = part, part+3, ...
// ---------------------------------------------------------------------------
__device__ void pre_body(int pb, float* sm,
    const float* __restrict__ rg, const float* __restrict__ kg,
    const float* __restrict__ vg, const float* __restrict__ wg,
    const float* __restrict__ bg)
{
    int bw = pb & 31, part = pb >> 5;
    int tid = threadIdx.x;
    float* sk  = sm;
    float* sv  = sk + 512;
    float* sw  = sv + 512;
    float* sb  = sw + 512;
    float* sr  = sb + 512;
    float* sgh = sr + 512;
    float* swx = sgh + 512;

    long long base = (long long)bw * 2048 * 64;

    for (int blk8 = part; blk8 < 256; blk8 += 3){
        long long off = base + (long long)blk8 * 512;
        for (int c = tid; c < 512; c += 256){
            sk[c] = kg[off+c]; sv[c] = vg[off+c]; sw[c] = wg[off+c];
            sb[c] = bg[off+c]; sr[c] = rg[off+c];
        }
        __syncthreads();

        float* gp = g_pre + (long long)(bw*256 + blk8) * PRE_STRIDE;

        if (tid < 64){
            int i = tid;
            float wx = 1.f;
#pragma unroll
            for (int t = 0; t < 8; t++){
                float wt   = sw[t*64+i];
                float winc = wx * wt;
                float gh   = __fdividef(sb[t*64+i]*sk[t*64+i], winc);
                sgh[t*64+i] = gh; swx[t*64+i] = wx;
                gp[OG +t*64+i] = gh;
                gp[OWX+t*64+i] = wx;
                gp[ORW+t*64+i] = sr[t*64+i]*winc;
                wx = winc;
            }
            gp[OW8+i] = wx;
        }
        else if (tid >= 128 && tid < 192){
            int idx = tid - 128;          // (t, tau) full 8x8
            int t = idx >> 3, ta = idx & 7;
            float acc = 0.f;
            int st = (idx & 31) * 2;
            for (int ii = 0; ii < 64; ii++){
                int i2 = (ii + st) & 63;
                acc += sv[t*64+i2]*sk[ta*64+i2];
            }
            gp[OP1+idx] = acc;
        }
        __syncthreads();

        if (tid < 84){
            int j = tid;
            int t = 1;
            if (j >= 7)  t = 2;
            if (j >= 19) t = 3;
            if (j >= 34) t = 4;
            if (j >= 50) t = 5;
            if (j >= 65) t = 6;
            if (j >= 77) t = 7;
            int rem = j - B84(t);
            int s   = rem / (8 - t);
            int ta  = t + rem % (8 - t);
            float acc = 0.f;
            int st = (tid & 15) * 4;
            for (int ii = 0; ii < 64; ii++){
                int i2 = (ii + st) & 63;
                acc += swx[t*64+i2]*sgh[s*64+i2]*sk[ta*64+i2];
            }
            gp[OT3+j] = acc;
        }
        __syncthreads();
        if (tid == 0){
            __threadfence();
            atomicExch(&g_ptask[bw*256 + blk8], 1);
        }
        __syncthreads();
    }
}

// ---------------------------------------------------------------------------
// WKV v6: 8-step WY blocks using precomputed gh/Wx/RW/W8/P1/T3.
// Thread (i = tid>>2 row, q = tid&3 -> 16 cols). 4 bars per 8 steps.
// ---------------------------------------------------------------------------
#define TSLOT  2048
#define KVSLOT 1024
#define OFF_KV (2*2*TSLOT)               // 8192
#define OFF_SM (OFF_KV + 2*2*KVSLOT)     // 12288
#define OFF_SP (OFF_SM + 512)            // 12800 (128 floats incl pad)
#define OFF_SA (OFF_SP + 128)            // 12928 (128)
#define OFF_SD (OFF_SA + 128)            // 13056 (512)
#define WKV_SM_FLOATS (OFF_SD + 512)     // 13568

__device__ void wkv_body(int bw, float* sh,
    const float* __restrict__ kg, const float* __restrict__ vg)
{
    float* preB = sh;
    float* kvB  = sh + OFF_KV;
    float* sM   = sh + OFF_SM;
    float* sP   = sh + OFF_SP;
    float* sA   = sh + OFF_SA;
    float* sD   = sh + OFF_SD;

    int bq = bw >> 4, h = bw & 15;
    int tid = threadIdx.x;
    int i = tid >> 2, q = tid & 3, j0 = q*16;
    int wid = tid >> 5, lane = tid & 31;

    long long base  = (long long)bw * 2048 * 64;
    long long obase = (long long)bq * 2048 * 1024 + h * 64;
    const float* kb = kg + base;
    const float* vb = vg + base;
    const int* ptk = g_ptask + bw*256;

    auto stage = [&](int n, int db){
        float* pd = preB + db*2*TSLOT;
        float* kd = kvB  + db*2*KVSLOT;
        const float* gpre = g_pre + (long long)(bw*256 + 2*n)*PRE_STRIDE;
#pragma unroll 1
        for (int c = tid; c < 1024; c += 256){
            int tsk = c >> 9, o = (c & 511) << 2;
            const float* src = gpre + (long long)tsk*PRE_STRIDE + o;
            unsigned du = (unsigned)__cvta_generic_to_shared(pd + tsk*TSLOT + o);
            asm volatile("cp.async.cg.shared.global [%0], [%1], 16;" :: "r"(du), "l"(src));
        }
#pragma unroll 1
        for (int c = tid; c < 512; c += 256){
            int tsk = (c >> 7) & 1, arr = c >> 8, o = (c & 127) << 2;
            const float* src = (arr ? vb : kb) + (long long)(2*n + tsk)*512 + o;
            unsigned du = (unsigned)__cvta_generic_to_shared(kd + tsk*KVSLOT + arr*512 + o);
            asm volatile("cp.async.cg.shared.global [%0], [%1], 16;" :: "r"(du), "l"(src));
        }
        asm volatile("cp.async.commit_group;" ::: "memory");
    };

    u64 S[8];
#pragma unroll
    for (int m = 0; m < 8; m++) S[m] = 0ull;

    // prologue: wait tasks 0,1 then stage tile 0
    if (tid == 0){
        while (ld_acq(&ptk[0]) == 0) __nanosleep(64);
        while (ld_acq(&ptk[1]) == 0) __nanosleep(64);
    }
    __syncthreads();
    stage(0, 0);

    for (int n = 0; n < 128; n++){
        int db = n & 1;
        if (n < 127){
            if (tid == 0){
                while (ld_acq(&ptk[2*n+2]) == 0) __nanosleep(64);
                while (ld_acq(&ptk[2*n+3]) == 0) __nanosleep(64);
            }
            __syncthreads();
            stage(n + 1, db ^ 1);
            asm volatile("cp.async.wait_group 1;" ::: "memory");
        } else {
            asm volatile("cp.async.wait_group 0;" ::: "memory");
        }
        __syncthreads();

        for (int half = 0; half < 2; half++){
            const float* tp = preB + db*2*TSLOT + half*TSLOT;
            const float* tk = kvB  + db*2*KVSLOT + half*KVSLOT;   // k @0, v @512
            int t0 = (2*n + half)*8;

            // ---- phase m: mp[t] = (S k_t)[i], reduced over 4 lanes ----
            float mp[8];
#pragma unroll
            for (int t = 0; t < 8; t++){
                const ulonglong2* kp = (const ulonglong2*)(tk + t*64 + j0);
                ulonglong2 K0 = kp[0], K1 = kp[1], K2 = kp[2], K3 = kp[3];
                u64 acc = fmul2(S[0], K0.x);
                acc = ffma2(S[1], K0.y, acc);
                acc = ffma2(S[2], K1.x, acc);
                acc = ffma2(S[3], K1.y, acc);
                acc = ffma2(S[4], K2.x, acc);
                acc = ffma2(S[5], K2.y, acc);
                acc = ffma2(S[6], K3.x, acc);
                acc = ffma2(S[7], K3.y, acc);
                float p = hadd2(acc);
                p += __shfl_xor_sync(0xffffffffu, p, 1);
                p += __shfl_xor_sync(0xffffffffu, p, 2);
                mp[t] = p;
            }
            if (q == 0){
#pragma unroll
                for (int t = 0; t < 8; t++) sM[t*64 + i] = mp[t];
            }
            __syncthreads();

            // ---- phase P2: sP[t][tau] = P1 - (Wx_t o m_t).k_tau ----
            {
                int p2 = tid >> 2;
                int t = p2 >> 3, ta = p2 & 7;
                const u64* wx2 = (const u64*)(tp + OWX + t*64 + j0);
                const u64* m2  = (const u64*)(sM + t*64 + j0);
                const u64* k2  = (const u64*)(tk + ta*64 + j0);
                u64 acc = 0ull;
#pragma unroll
                for (int m = 0; m < 8; m++)
                    acc = ffma2(fmul2(wx2[m], m2[m]), k2[m], acc);
                float pv = hadd2(acc);
                pv += __shfl_xor_sync(0xffffffffu, pv, 1);
                pv += __shfl_xor_sync(0xffffffffu, pv, 2);
                if (q == 0) sP[p2] = tp[OP1 + p2] - pv;
            }
            __syncthreads();

            // ---- solve (warp 0): A[t][tau] scalars ----
            if (wid == 0){
                float A[8];
#pragma unroll
                for (int t = 0; t < 8; t++){
                    float acc = sP[t*8 + (lane & 7)];
#pragma unroll
                    for (int s = 0; s < 8; s++){
                        if (s < t){
                            float Ast = __shfl_sync(0xffffffffu, A[s], t);
                            int dt = (lane >= t && lane < 8) ? (lane - t) : 0;
                            int ix = B84(t) + s*(8 - t) + dt;
                            acc -= tp[OT3 + ix]*Ast;
                        }
                    }
                    A[t] = acc;
                }
#pragma unroll
                for (int s = 0; s < 8; s++)
                    if (lane < 8 && lane >= s) sA[s*8 + lane] = A[s];
            }
            __syncthreads();

            // ---- delta + y (q==0 lanes, per row i) ----
            if (q == 0){
                float ct[8];
#pragma unroll
                for (int t = 0; t < 8; t++) ct[t] = 0.f;
#pragma unroll
                for (int s = 0; s < 7; s++){
                    float ghs = tp[OG + s*64 + i];
#pragma unroll
                    for (int t = s + 1; t < 8; t++)
                        ct[t] += ghs*sA[s*8 + t];
                }
#pragma unroll
                for (int t = 0; t < 8; t++){
                    float mt  = mp[t] + ct[t];
                    float del = tk[512 + t*64 + i] - tp[OWX + t*64 + i]*mt;
                    sD[t*64 + i] = del;
                    float y = tp[ORW + t*64 + i]*(mt + tp[OG + t*64 + i]*sA[t*8 + t]);
                    g_y[obase + (long long)(t0 + t)*1024 + i] = y;
                }
            }
            __syncthreads();

            // ---- rank-8 state update + decay scale ----
#pragma unroll
            for (int t = 0; t < 8; t++){
                u64 g2 = dup2(tp[OG + t*64 + i]);
                const ulonglong2* dp = (const ulonglong2*)(sD + t*64 + j0);
                ulonglong2 D0 = dp[0], D1 = dp[1], D2 = dp[2], D3 = dp[3];
                S[0] = ffma2(g2, D0.x, S[0]);
                S[1] = ffma2(g2, D0.y, S[1]);
                S[2] = ffma2(g2, D1.x, S[2]);
                S[3] = ffma2(g2, D1.y, S[3]);
                S[4] = ffma2(g2, D2.x, S[4]);
                S[5] = ffma2(g2, D2.y, S[5]);
                S[6] = ffma2(g2, D3.x, S[6]);
                S[7] = ffma2(g2, D3.y, S[7]);
            }
            {
                u64 w8 = dup2(tp[OW8 + i]);
#pragma unroll
                for (int m = 0; m < 8; m++) S[m] = fmul2(w8, S[m]);
            }
        }

        if ((n & 3) == 3){
            __threadfence();
            __syncthreads();
            if (tid == 0) atomicAdd(&g_prog[bw], 1);
        }
    }
}

// ---------------------------------------------------------------------------
// Cross-chunk state scan (unchanged).
// ---------------------------------------------------------------------------
__device__ void scan_body(int bh, float* sm, const float* __restrict__ Ag)
{
    int b = bh >> 4, h = bh & 15;
    float* atot = sm;
    int tid = threadIdx.x;
    if (tid < 32){
        float s = 0.f;
        long long base = ((long long)b*2048 + tid*64)*16 + h;
        for (int l = 0; l < 64; l++) s += Ag[base + (long long)l*16];
        atot[tid] = s;
    }
    __syncthreads();
    float S[16];
#pragma unroll
    for (int i = 0; i < 16; i++) S[i] = 0.f;
    float* base = g_states + (long long)bh*32*4096;
    for (int c = 0; c < 32; c++){
        float dec = expf(atot[c]);
        float* p = base + (long long)c*4096;
#pragma unroll
        for (int r2 = 0; r2 < 16; r2++){
            int e = r2*256 + tid;
            float st = p[e];
            p[e] = S[r2];
            S[r2] = S[r2]*dec + st;
        }
    }
    __syncthreads();
}

// ---------------------------------------------------------------------------
// Y_off + g_y add for one (b,h,c) (unchanged).
// ---------------------------------------------------------------------------
__device__ void yoff_chunk(int bh, int c, float* sm,
    const float* __restrict__ Ag, const float* __restrict__ Cg,
    float* __restrict__ out)
{
    float* sC   = sm;
    float* sS   = sC + 64*PADW;
    float* sCum = sS + 64*PADW;
    int b  = bh >> 4, h = bh & 15;
    int tid = threadIdx.x;
    long long gbase = ((long long)b*2048 + c*64)*1024 + h*64;
    const float* st = g_states + ((long long)bh*32 + c)*4096;

    for (int e = tid; e < 4096; e += 256){
        int l = e >> 6, p = e & 63;
        sC[l*PADW + p] = Cg[gbase + (long long)l*1024 + p];
        sS[p*PADW + l] = st[(l << 6) | p];
    }
    if (tid < 64) sCum[tid] = Ag[((long long)b*2048 + c*64 + tid)*16 + h];
    __syncthreads();
    if (tid == 0){
        float run = 0.f;
        for (int l = 0; l < 64; l++){ run += sCum[l]; sCum[l] = run; }
    }
    __syncthreads();

    int l  = tid >> 2;
    int pg = tid & 3;
    float acc[16];
#pragma unroll
    for (int i = 0; i < 16; i++) acc[i] = 0.f;
    for (int n = 0; n < 64; n++){
        float cv = sC[l*PADW + n];
        const float4* s4 = (const float4*)(sS + n*PADW) + pg*4;
#pragma unroll
        for (int q4 = 0; q4 < 4; q4++){
            float4 sv = s4[q4];
            acc[q4*4+0] += cv*sv.x;
            acc[q4*4+1] += cv*sv.y;
            acc[q4*4+2] += cv*sv.z;
            acc[q4*4+3] += cv*sv.w;
        }
    }
    float d = expf(sCum[l]);
    float4* op = (float4*)(out + gbase + (long long)l*1024 + pg*16);
    const float4* gp = (const float4*)(g_y + gbase + (long long)l*1024 + pg*16);
#pragma unroll
    for (int q4 = 0; q4 < 4; q4++){
        float4 ov = op[q4];
        float4 gv = gp[q4];
        ov.x += d*acc[q4*4+0] + gv.x;
        ov.y += d*acc[q4*4+1] + gv.y;
        ov.z += d*acc[q4*4+2] + gv.z;
        ov.w += d*acc[q4*4+3] + gv.w;
        op[q4] = ov;
    }
    __syncthreads();
}

// ---------------------------------------------------------------------------
// Single launch, grid = 1184:
//   0..95      : WY precompute (fast, wave-1 resident)
//   96..127    : wkv (isolated 1 block/SM via 120KB smem)
//   128..1151  : ssd chunks -> release c1
//   1152..1183 : scan + yoff (trailing wkv progress) + cleanup
// ---------------------------------------------------------------------------
__global__ __launch_bounds__(256) void fused_kernel(
    const float* __restrict__ Xg, const float* __restrict__ Ag,
    const float* __restrict__ Bg, const float* __restrict__ Cg,
    const float* __restrict__ rg, const float* __restrict__ kg,
    const float* __restrict__ vg, const float* __restrict__ wg,
    const float* __restrict__ bg, float* __restrict__ out)
{
    extern __shared__ float sm[];
    int tid = threadIdx.x;

    if (blockIdx.x < 96){
        pre_body(blockIdx.x, sm, rg, kg, vg, wg, bg);
    }
    else if (blockIdx.x < 128){
        wkv_body(blockIdx.x - 96, sm, kg, vg);
    }
    else if (blockIdx.x < 1152){
        ssd_chunk_body(blockIdx.x - 128, sm, Xg, Ag, Bg, Cg, out);
        __threadfence();
        __syncthreads();
        if (tid == 0) atomicAdd(&g_c1, 1);
    }
    else {
        int bh = blockIdx.x - 1152;
        if (tid == 0){
            while (ld_acq(&g_c1) < 1024) __nanosleep(128);
        }
        __syncthreads();
        scan_body(bh, sm, Ag);
        for (int c = 0; c < 32; c++){
            if (tid == 0){
                while (ld_acq(&g_prog[bh]) <= c) __nanosleep(128);
            }
            __syncthreads();
            yoff_chunk(bh, c, sm, Ag, Cg, out);
        }
        // cleanup for next graph replay
        g_ptask[bh*256 + tid] = 0;
        __threadfence();
        __syncthreads();
        if (tid == 0){
            g_prog[bh] = 0;
            int done = atomicAdd(&g_c2, 1);
            if (done == 31){ g_c1 = 0; g_c2 = 0; }
        }
    }
}

// ---------------------------------------------------------------------------
extern "C" void kernel_launch(void* const* d_in, const int* in_sizes, int n_in,
                              void* d_out, int out_size)
{
    const float* X  = (const float*)d_in[0];
    const float* A  = (const float*)d_in[1];
    const float* B  = (const float*)d_in[2];
    const float* C  = (const float*)d_in[3];
    const float* r  = (const float*)d_in[4];
    const float* k  = (const float*)d_in[5];
    const float* v  = (const float*)d_in[6];
    const float* w  = (const float*)d_in[7];
    const float* bn = (const float*)d_in[8];
    float* out = (float*)d_out;

    const size_t smemF = 120 * 1024;   // 1 block/SM: wkv SMs stay isolated
    cudaFuncSetAttribute(fused_kernel,
                         cudaFuncAttributeMaxDynamicSharedMemorySize, (int)smemF);

    fused_kernel<<<1184, 256, smemF>>>(X, A, B, C, r, k, v, w, bn, out);
}